// round 8
// baseline (speedup 1.0000x reference)
#include <cuda_runtime.h>
#include <cuda_fp16.h>
#include <cstdint>

// RNN: h_t = tanh([h_{t-1} | x_t] @ [W_hh | W_ih]^T + b), out = h_T @ W_out^T + b_out
// Round 8: BTILE=4, folded-n fp16-split. B-tile rows 0-3 = s_hi, rows 4-7 = s_lo*2048.
//   pass1: accA += W_hi*B   (rows 0-3: hi*hi, rows 4-7: hi*lo)
//   pass2: accB += W_lo*B   (rows 0-3: lo*hi; rows 4-7 garbage)
//   h(n) = tanh( accA[n] + (accA[n+4] + accB[n])/2048 ),  bias*2048 pre-folded into accB.
// 2 mma passes (24 mma/warp-step), 12 LDS/warp-step, ~140 regs -> 7 CTAs/SM no spill.

#define BATCH    4096
#define TSTEPS   512
#define IN_DIM   28
#define HID      64
#define OUT_DIM  10
#define KCOMB    96           // 64 h + 28 x + 4 pad
#define CHUNKS   6            // KCOMB / 16
#define BTILE    4            // active batch rows per CTA
#define NTHREADS 64           // 2 warps, each m=32
#define S        68           // words per n-row; 68 % 32 == 4 -> conflict-free B loads
#define PLANE    (8 * S)      // 544 words: one buffer (8 n-rows: 4 hi + 4 lo)
#define STATE_WORDS (2 * PLANE)         // 1088 (double buffer)
#define BIAS_OFF (HID * KCOMB)          // 6144 (past state overlay, inside smem)
#define SMEM_WORDS (BIAS_OFF + HID)     // 6208
#define SMEM_BYTES (SMEM_WORDS * 4)     // 24832 B -> 7 CTAs/SM by smem
#define WOUT_OFF 1152                   // W_out stage for epilogue (past state)

#define INV2048  4.8828125e-4f

__device__ __forceinline__ float fast_tanh(float v) {
    float e = __expf(2.0f * v);
    return 1.0f - __fdividef(2.0f, e + 1.0f);
}

__device__ __forceinline__ uint32_t pack2(__half lo, __half hi) {
    __half2 h = __halves2half2(lo, hi);
    return *reinterpret_cast<uint32_t*>(&h);
}

__device__ __forceinline__ void mma16(float* d, const uint32_t* a, const uint32_t* b) {
    asm volatile(
        "mma.sync.aligned.m16n8k16.row.col.f32.f16.f16.f32 "
        "{%0,%1,%2,%3}, {%4,%5,%6,%7}, {%8,%9}, {%0,%1,%2,%3};"
        : "+f"(d[0]), "+f"(d[1]), "+f"(d[2]), "+f"(d[3])
        : "r"(a[0]), "r"(a[1]), "r"(a[2]), "r"(a[3]), "r"(b[0]), "r"(b[1]));
}

__global__ void __launch_bounds__(NTHREADS, 7)
rnn_fold_kernel(const float* __restrict__ x,
                const float* __restrict__ W_ih,
                const float* __restrict__ W_hh,
                const float* __restrict__ b_ih,
                const float* __restrict__ b_hh,
                const float* __restrict__ W_out,
                const float* __restrict__ b_out,
                float* __restrict__ out)
{
    extern __shared__ float sm[];
    uint32_t* usm = (uint32_t*)sm;

    const int tid  = threadIdx.x;
    const int b0   = blockIdx.x * BTILE;
    const int lane = tid & 31;
    const int mg   = tid >> 5;     // warp id = m-group: W rows [mg*32, mg*32+32)
    const int gid  = lane >> 2;
    const int tig  = lane & 3;
    const int m0b  = mg * 32;

    // ---- Stage combined weight Wc[64][96] fp32 at sm[0..6144) + bias ----
    for (int idx = tid; idx < HID * KCOMB; idx += NTHREADS) {
        int j = idx / KCOMB, k = idx % KCOMB;
        float v = 0.0f;
        if (k < HID)               v = W_hh[j * HID + k];
        else if (k < HID + IN_DIM) v = W_ih[j * IN_DIM + (k - HID)];
        sm[idx] = v;
    }
    if (tid < HID) sm[BIAS_OFF + tid] = b_ih[tid] + b_hh[tid];
    __syncthreads();

    // ---- W fragments (A operand, m16k16), hi + scaled-lo fp16 ----
    uint32_t whi[2][CHUNKS][4], wlo[2][CHUNKS][4];
    float bias2048[2][2];                 // bias * 2048, pre-folded into accB init
#pragma unroll
    for (int mt = 0; mt < 2; mt++) {
        int m0 = m0b + mt * 16;
#pragma unroll
        for (int c = 0; c < CHUNKS; c++) {
#pragma unroll
            for (int r = 0; r < 4; r++) {
                int row = m0 + gid + (r & 1) * 8;
                int k0  = c * 16 + 2 * tig + (r >> 1) * 8;
                float va = sm[row * KCOMB + k0];
                float vb = sm[row * KCOMB + k0 + 1];
                __half ha = __float2half_rn(va), hb = __float2half_rn(vb);
                whi[mt][c][r] = pack2(ha, hb);
                wlo[mt][c][r] = pack2(
                    __float2half_rn((va - __half2float(ha)) * 2048.0f),
                    __float2half_rn((vb - __half2float(hb)) * 2048.0f));
            }
        }
        bias2048[mt][0] = sm[BIAS_OFF + m0 + gid] * 2048.0f;
        bias2048[mt][1] = sm[BIAS_OFF + m0 + gid + 8] * 2048.0f;
    }
    __syncthreads();   // frag reads done; stage area reused as state

    // ---- Zero state double-buffers (h=0, lo=0, pads 0) ----
    for (int idx = tid; idx < STATE_WORDS; idx += NTHREADS) sm[idx] = 0.0f;

    // ---- x loader: 28 threads, one float4 (4 k-values of one row) per step ----
    const bool isld = tid < 28;
    const int  xn = isld ? tid / 7 : 0;       // row 0..3
    const int  xq = isld ? tid % 7 : 0;
    const float4* xp4 = (const float4*)(x + (size_t)(b0 + xn) * TSTEPS * IN_DIM) + xq;

    float4 xr = make_float4(0, 0, 0, 0);
    if (isld) xr = xp4[0];                    // t = 0
    __syncthreads();                          // zero-fill visible

    // x_hi -> row xn, x_lo*2048 -> row xn+4 (k words 32 + 2*xq, +1)
    auto store_x = [&](int p) {
        int hb = p * PLANE + xn * S + 32 + 2 * xq;
        __half h0 = __float2half_rn(xr.x), h1 = __float2half_rn(xr.y);
        __half h2 = __float2half_rn(xr.z), h3 = __float2half_rn(xr.w);
        usm[hb]     = pack2(h0, h1);
        usm[hb + 1] = pack2(h2, h3);
        usm[hb + 4 * S]     = pack2(__float2half_rn((xr.x - __half2float(h0)) * 2048.0f),
                                    __float2half_rn((xr.y - __half2float(h1)) * 2048.0f));
        usm[hb + 4 * S + 1] = pack2(__float2half_rn((xr.z - __half2float(h2)) * 2048.0f),
                                    __float2half_rn((xr.w - __half2float(h3)) * 2048.0f));
    };
    if (isld) store_x(0);
    __syncthreads();

    const bool evengid = !(gid & 1);
    const bool dostore = (tig < 2);           // result rows 2*tig, 2*tig+1 (0..3)
    const int  n0 = 2 * tig;

    int p = 0;
    for (int t = 0; t < TSTEPS; t++) {
        if (isld && t + 1 < TSTEPS) xr = xp4[(t + 1) * 7];   // prefetch

        float accA[2][4], accB[2][4];
#pragma unroll
        for (int mt = 0; mt < 2; mt++) {
            accA[mt][0] = 0.0f; accA[mt][1] = 0.0f;
            accA[mt][2] = 0.0f; accA[mt][3] = 0.0f;
            accB[mt][0] = bias2048[mt][0]; accB[mt][1] = bias2048[mt][0];
            accB[mt][2] = bias2048[mt][1]; accB[mt][3] = bias2048[mt][1];
        }

        const int hbase = p * PLANE + gid * S;   // n-row = gid (0..7)
#pragma unroll
        for (int c = 0; c < CHUNKS; c++) {
            uint32_t b[2];
            b[0] = usm[hbase + c * 8 + tig];
            b[1] = usm[hbase + c * 8 + tig + 4];
            mma16(accA[0], whi[0][c], b);
            mma16(accA[1], whi[1][c], b);
            mma16(accB[0], wlo[0][c], b);
            mma16(accB[1], wlo[1][c], b);
        }

        const int q = p ^ 1;
#pragma unroll
        for (int mt = 0; mt < 2; mt++) {
            // fold: bring accA rows n+4 (held by tig^2 partner) down to rows n
            float f0 = __shfl_xor_sync(0xffffffffu, accA[mt][0], 2);
            float f1 = __shfl_xor_sync(0xffffffffu, accA[mt][1], 2);
            float f2 = __shfl_xor_sync(0xffffffffu, accA[mt][2], 2);
            float f3 = __shfl_xor_sync(0xffffffffu, accA[mt][3], 2);

            float v0 = 0.0f, v1 = 0.0f, v2 = 0.0f, v3 = 0.0f;
            if (dostore) {
                v0 = fast_tanh(accA[mt][0] + (f0 + accB[mt][0]) * INV2048);
                v1 = fast_tanh(accA[mt][1] + (f1 + accB[mt][1]) * INV2048);
                v2 = fast_tanh(accA[mt][2] + (f2 + accB[mt][2]) * INV2048);
                v3 = fast_tanh(accA[mt][3] + (f3 + accB[mt][3]) * INV2048);
            }

            // j-pair exchange across lane^4 (same tig, flips gid parity)
            float s0 = evengid ? v2 : v0;
            float s1 = evengid ? v3 : v1;
            float r0 = __shfl_xor_sync(0xffffffffu, s0, 4);
            float r1 = __shfl_xor_sync(0xffffffffu, s1, 4);

            if (dostore) {
                int m0 = m0b + mt * 16;
                int kp = evengid ? ((m0 + gid) >> 1) : ((m0 + gid + 7) >> 1);
                float a0 = evengid ? v0 : r0;   // lower-j value, row n0
                float c0 = evengid ? r0 : v2;   // upper-j value, row n0
                float a1 = evengid ? v1 : r1;   // row n0+1
                float c1 = evengid ? r1 : v3;

                __half ha0 = __float2half_rn(a0), hc0 = __float2half_rn(c0);
                __half ha1 = __float2half_rn(a1), hc1 = __float2half_rn(c1);
                int whb = q * PLANE + n0 * S + kp;
                usm[whb]     = pack2(ha0, hc0);                       // hi, row n0
                usm[whb + S] = pack2(ha1, hc1);                       // hi, row n0+1
                usm[whb + 4 * S]     = pack2(                          // lo, row n0+4
                    __float2half_rn((a0 - __half2float(ha0)) * 2048.0f),
                    __float2half_rn((c0 - __half2float(hc0)) * 2048.0f));
                usm[whb + 5 * S]     = pack2(                          // lo, row n0+5
                    __float2half_rn((a1 - __half2float(ha1)) * 2048.0f),
                    __float2half_rn((c1 - __half2float(hc1)) * 2048.0f));
            }
        }

        if (isld && t + 1 < TSTEPS) store_x(q);
        __syncthreads();
        p = q;
    }

    // ---- Output projection: stage W_out past state region ----
    for (int idx = tid; idx < OUT_DIM * HID; idx += NTHREADS) sm[WOUT_OFF + idx] = W_out[idx];
    if (tid < OUT_DIM) sm[WOUT_OFF + OUT_DIM * HID + tid] = b_out[tid];
    __syncthreads();

    const int hb = p * PLANE;
    for (int idx = tid; idx < BTILE * OUT_DIM; idx += NTHREADS) {
        int n = idx / OUT_DIM, o = idx % OUT_DIM;
        float s = sm[WOUT_OFF + OUT_DIM * HID + o];
#pragma unroll 8
        for (int jp = 0; jp < HID / 2; jp++) {
            __half2 hh = *reinterpret_cast<const __half2*>(&usm[hb + n * S + jp]);
            __half2 ll = *reinterpret_cast<const __half2*>(&usm[hb + (n + 4) * S + jp]);
            float2 fh = __half22float2(hh), fl = __half22float2(ll);
            s += (fh.x + fl.x * INV2048) * sm[WOUT_OFF + o * HID + 2 * jp]
               + (fh.y + fl.y * INV2048) * sm[WOUT_OFF + o * HID + 2 * jp + 1];
        }
        out[(size_t)(b0 + n) * OUT_DIM + o] = s;
    }
}

extern "C" void kernel_launch(void* const* d_in, const int* in_sizes, int n_in,
                              void* d_out, int out_size)
{
    const float* x     = (const float*)d_in[0];
    const float* W_ih  = (const float*)d_in[1];
    const float* W_hh  = (const float*)d_in[2];
    const float* b_ih  = (const float*)d_in[3];
    const float* b_hh  = (const float*)d_in[4];
    const float* W_out = (const float*)d_in[5];
    const float* b_out = (const float*)d_in[6];
    float* out = (float*)d_out;

    cudaFuncSetAttribute(rnn_fold_kernel,
                         cudaFuncAttributeMaxDynamicSharedMemorySize, SMEM_BYTES);

    dim3 grid(BATCH / BTILE);   // 1024 CTAs, 4 persistent batch rows each
    dim3 block(NTHREADS);       // 2 warps
    rnn_fold_kernel<<<grid, block, SMEM_BYTES>>>(x, W_ih, W_hh, b_ih, b_hh,
                                                 W_out, b_out, out);
}

// round 9
// speedup vs baseline: 2.1950x; 2.1950x over previous
#include <cuda_runtime.h>
#include <cuda_fp16.h>
#include <cstdint>

// RNN: h_t = tanh([h_{t-1} | x_t] @ [W_hh | W_ih]^T + b), out = h_T @ W_out^T + b_out
// fp16-split 3-pass mma.m16n8k16: W = W_hi + W_lo/2048, state likewise.
// acc = W_hi*s_hi + (W_lo*s_hi + W_hi*s_lo)/2048; dropped lo*lo ~ 2^-22.
// Round 9: BTILE=8, 512 CTAs, 4 warps x m=16 (48 W regs/warp, ~95 total -> no spill),
// occupancy 4 CTAs/SM, 3.46 warps/SMSP (2x round 6), single wave.

#define BATCH    4096
#define TSTEPS   512
#define IN_DIM   28
#define HID      64
#define OUT_DIM  10
#define KCOMB    96           // 64 h + 28 x + 4 pad
#define CHUNKS   6            // KCOMB / 16
#define BTILE    8
#define NTHREADS 128          // 4 warps, each m=16, n=8 (all rows)
#define S        68           // words per row; 68 % 32 == 4 -> conflict-free maps
#define PLANE    (BTILE * S)  // 544 words per plane
#define STATE_WORDS (4 * PLANE)         // 2176: [buf0_hi|buf0_lo|buf1_hi|buf1_lo]
#define BIAS_OFF (HID * KCOMB)          // 6144 (stage area, overlaid by state later)
#define SMEM_WORDS (BIAS_OFF + HID)     // 6208
#define SMEM_BYTES (SMEM_WORDS * 4)     // 24832 B
#define WOUT_OFF 2304                   // W_out stage for epilogue (past state)

#define INV2048  4.8828125e-4f

__device__ __forceinline__ float fast_tanh(float v) {
    float e = __expf(2.0f * v);
    return 1.0f - __fdividef(2.0f, e + 1.0f);
}

__device__ __forceinline__ uint32_t pack2(__half lo, __half hi) {
    __half2 h = __halves2half2(lo, hi);
    return *reinterpret_cast<uint32_t*>(&h);
}

__device__ __forceinline__ void mma16(float* d, const uint32_t* a, const uint32_t* b) {
    asm volatile(
        "mma.sync.aligned.m16n8k16.row.col.f32.f16.f16.f32 "
        "{%0,%1,%2,%3}, {%4,%5,%6,%7}, {%8,%9}, {%0,%1,%2,%3};"
        : "+f"(d[0]), "+f"(d[1]), "+f"(d[2]), "+f"(d[3])
        : "r"(a[0]), "r"(a[1]), "r"(a[2]), "r"(a[3]), "r"(b[0]), "r"(b[1]));
}

__global__ void __launch_bounds__(NTHREADS, 4)
rnn_w4_kernel(const float* __restrict__ x,
              const float* __restrict__ W_ih,
              const float* __restrict__ W_hh,
              const float* __restrict__ b_ih,
              const float* __restrict__ b_hh,
              const float* __restrict__ W_out,
              const float* __restrict__ b_out,
              float* __restrict__ out)
{
    extern __shared__ float sm[];
    uint32_t* usm = (uint32_t*)sm;

    const int tid  = threadIdx.x;
    const int b0   = blockIdx.x * BTILE;
    const int lane = tid & 31;
    const int mg   = tid >> 5;     // warp id = m-group: W rows [mg*16, mg*16+16)
    const int gid  = lane >> 2;
    const int tig  = lane & 3;
    const int m0   = mg * 16;

    // ---- Stage combined weight Wc[64][96] fp32 at sm[0..6144) + bias ----
    for (int idx = tid; idx < HID * KCOMB; idx += NTHREADS) {
        int j = idx / KCOMB, k = idx % KCOMB;
        float v = 0.0f;
        if (k < HID)               v = W_hh[j * HID + k];
        else if (k < HID + IN_DIM) v = W_ih[j * IN_DIM + (k - HID)];
        sm[idx] = v;
    }
    if (tid < HID) sm[BIAS_OFF + tid] = b_ih[tid] + b_hh[tid];
    __syncthreads();

    // ---- W fragments (A operand, one m16k16 tile per warp), hi + scaled-lo fp16 ----
    uint32_t whi[CHUNKS][4], wlo[CHUNKS][4];
#pragma unroll
    for (int c = 0; c < CHUNKS; c++) {
#pragma unroll
        for (int r = 0; r < 4; r++) {
            int row = m0 + gid + (r & 1) * 8;
            int k0  = c * 16 + 2 * tig + (r >> 1) * 8;
            float va = sm[row * KCOMB + k0];
            float vb = sm[row * KCOMB + k0 + 1];
            __half ha = __float2half_rn(va), hb = __float2half_rn(vb);
            whi[c][r] = pack2(ha, hb);
            wlo[c][r] = pack2(
                __float2half_rn((va - __half2float(ha)) * 2048.0f),
                __float2half_rn((vb - __half2float(hb)) * 2048.0f));
        }
    }
    const float bias0 = sm[BIAS_OFF + m0 + gid];
    const float bias1 = sm[BIAS_OFF + m0 + gid + 8];
    __syncthreads();   // frag reads done; stage area reused as state

    // ---- Zero state double-buffers overlaid on stage area ----
    for (int idx = tid; idx < STATE_WORDS; idx += NTHREADS) sm[idx] = 0.0f;

    // ---- x loader: 56 threads, one float4 (4 k-values of one row) per step ----
    const bool isld = tid < 56;
    const int  xn = isld ? tid / 7 : 0;       // row 0..7
    const int  xq = isld ? tid % 7 : 0;
    const float4* xp4 = (const float4*)(x + (size_t)(b0 + xn) * TSTEPS * IN_DIM) + xq;

    float4 xr = make_float4(0, 0, 0, 0);
    if (isld) xr = xp4[0];                    // t = 0
    __syncthreads();                          // zero-fill visible

    auto store_x = [&](int p) {
        int hb = (p * 2) * PLANE + xn * S + 32 + 2 * xq;
        __half h0 = __float2half_rn(xr.x), h1 = __float2half_rn(xr.y);
        __half h2 = __float2half_rn(xr.z), h3 = __float2half_rn(xr.w);
        usm[hb]     = pack2(h0, h1);
        usm[hb + 1] = pack2(h2, h3);
        usm[hb + PLANE]     = pack2(__float2half_rn((xr.x - __half2float(h0)) * 2048.0f),
                                    __float2half_rn((xr.y - __half2float(h1)) * 2048.0f));
        usm[hb + PLANE + 1] = pack2(__float2half_rn((xr.z - __half2float(h2)) * 2048.0f),
                                    __float2half_rn((xr.w - __half2float(h3)) * 2048.0f));
    };
    if (isld) store_x(0);
    __syncthreads();

    const bool evengid = !(gid & 1);
    const int  n0 = 2 * tig;                  // batch rows n0, n0+1 (0..7)

    int p = 0;
    for (int t = 0; t < TSTEPS; t++) {
        if (isld && t + 1 < TSTEPS) xr = xp4[(t + 1) * 7];   // prefetch

        // 3 independent accumulation chains, depth 6 each
        float accA[4], accB1[4], accB2[4];
        accA[0] = bias0; accA[1] = bias0; accA[2] = bias1; accA[3] = bias1;
#pragma unroll
        for (int r = 0; r < 4; r++) { accB1[r] = 0.0f; accB2[r] = 0.0f; }

        const int hbase = (p * 2) * PLANE + gid * S;   // n-row = gid (0..7)
        const int lbase = hbase + PLANE;
#pragma unroll
        for (int c = 0; c < CHUNKS; c++) {
            uint32_t bh[2], bl[2];
            bh[0] = usm[hbase + c * 8 + tig];
            bh[1] = usm[hbase + c * 8 + tig + 4];
            bl[0] = usm[lbase + c * 8 + tig];
            bl[1] = usm[lbase + c * 8 + tig + 4];
            mma16(accA,  whi[c], bh);
            mma16(accB1, wlo[c], bh);
            mma16(accB2, whi[c], bl);
        }

        // tanh -> shfl-pair -> fp16-split -> store into buffer q
        const int q = p ^ 1;
        float v0 = fast_tanh(accA[0] + (accB1[0] + accB2[0]) * INV2048);
        float v1 = fast_tanh(accA[1] + (accB1[1] + accB2[1]) * INV2048);
        float v2 = fast_tanh(accA[2] + (accB1[2] + accB2[2]) * INV2048);
        float v3 = fast_tanh(accA[3] + (accB1[3] + accB2[3]) * INV2048);

        // exchange across j-pair partner (lane ^ 4, same tig)
        float s0 = evengid ? v2 : v0;
        float s1 = evengid ? v3 : v1;
        float r0 = __shfl_xor_sync(0xffffffffu, s0, 4);
        float r1 = __shfl_xor_sync(0xffffffffu, s1, 4);

        {
            int kp = evengid ? ((m0 + gid) >> 1) : ((m0 + gid + 7) >> 1);
            float a0 = evengid ? v0 : r0;   // lower-j value, row n0
            float c0 = evengid ? r0 : v2;   // upper-j value, row n0
            float a1 = evengid ? v1 : r1;   // row n0+1
            float c1 = evengid ? r1 : v3;

            __half ha0 = __float2half_rn(a0), hc0 = __float2half_rn(c0);
            __half ha1 = __float2half_rn(a1), hc1 = __float2half_rn(c1);
            int whb = (q * 2) * PLANE + n0 * S + kp;
            usm[whb]     = pack2(ha0, hc0);
            usm[whb + S] = pack2(ha1, hc1);
            usm[whb + PLANE]     = pack2(__float2half_rn((a0 - __half2float(ha0)) * 2048.0f),
                                         __float2half_rn((c0 - __half2float(hc0)) * 2048.0f));
            usm[whb + PLANE + S] = pack2(__float2half_rn((a1 - __half2float(ha1)) * 2048.0f),
                                         __float2half_rn((c1 - __half2float(hc1)) * 2048.0f));
        }

        if (isld && t + 1 < TSTEPS) store_x(q);
        __syncthreads();
        p = q;
    }

    // ---- Output projection: stage W_out past the state region ----
    for (int idx = tid; idx < OUT_DIM * HID; idx += NTHREADS) sm[WOUT_OFF + idx] = W_out[idx];
    if (tid < OUT_DIM) sm[WOUT_OFF + OUT_DIM * HID + tid] = b_out[tid];
    __syncthreads();

    const int hb = (p * 2) * PLANE;
    for (int idx = tid; idx < BTILE * OUT_DIM; idx += NTHREADS) {
        int n = idx / OUT_DIM, o = idx % OUT_DIM;
        float s = sm[WOUT_OFF + OUT_DIM * HID + o];
#pragma unroll 8
        for (int jp = 0; jp < HID / 2; jp++) {
            __half2 hh = *reinterpret_cast<const __half2*>(&usm[hb + n * S + jp]);
            __half2 ll = *reinterpret_cast<const __half2*>(&usm[hb + PLANE + n * S + jp]);
            float2 fh = __half22float2(hh), fl = __half22float2(ll);
            s += (fh.x + fl.x * INV2048) * sm[WOUT_OFF + o * HID + 2 * jp]
               + (fh.y + fl.y * INV2048) * sm[WOUT_OFF + o * HID + 2 * jp + 1];
        }
        out[(size_t)(b0 + n) * OUT_DIM + o] = s;
    }
}

extern "C" void kernel_launch(void* const* d_in, const int* in_sizes, int n_in,
                              void* d_out, int out_size)
{
    const float* x     = (const float*)d_in[0];
    const float* W_ih  = (const float*)d_in[1];
    const float* W_hh  = (const float*)d_in[2];
    const float* b_ih  = (const float*)d_in[3];
    const float* b_hh  = (const float*)d_in[4];
    const float* W_out = (const float*)d_in[5];
    const float* b_out = (const float*)d_in[6];
    float* out = (float*)d_out;

    cudaFuncSetAttribute(rnn_w4_kernel,
                         cudaFuncAttributeMaxDynamicSharedMemorySize, SMEM_BYTES);

    dim3 grid(BATCH / BTILE);   // 512 CTAs, 8 persistent batch rows each
    dim3 block(NTHREADS);       // 4 warps, each m=16
    rnn_w4_kernel<<<grid, block, SMEM_BYTES>>>(x, W_ih, W_hh, b_ih, b_hh,
                                               W_out, b_out, out);
}